// round 5
// baseline (speedup 1.0000x reference)
#include <cuda_runtime.h>
#include <cuda_bf16.h>
#include <cstdint>
#include <math_constants.h>

#define N_  64
#define C_  8
#define L_  2048
#define S_  64
#define K_  128
#define W_  (L_ - S_ + 1)          /* 1985 */
#define WT  64                     /* windows per block */
#define NWT ((W_ + WT - 1) / WT)   /* 32 */
#define PAD 72                     /* row pitch in bf16 (144B): conflict-free ldmatrix */

// ---- dynamic smem layout (bytes) ----
#define O_B      0                 /* 18432: B tile (128k x 64s bf16, padded) */
#define O_A      18432             /* 9216:  A tile (64w x 64s bf16, padded)  */
#define O_STRIP  27648             /* 512:   128 f32                          */
#define O_SQX    28160             /* 256:   64 f32                           */
#define BUFSZ    28416
#define SM_MIN   56832             /* 128 int */
#define SM_TOTAL 57344

// ---------------- device scratch ----------------
__device__ __align__(16) __nv_bfloat16 g_shb[C_][K_ * PAD]; // z-normed shapelets, padded rows

// ---------------- helpers ----------------
__device__ __forceinline__ uint32_t smem_u32(const void* p) {
    uint32_t a;
    asm("{ .reg .u64 t; cvta.to.shared.u64 t, %1; cvt.u32.u64 %0, t; }" : "=r"(a) : "l"(p));
    return a;
}
__device__ __forceinline__ float fast_sqrt(float x) {
    float r; asm("sqrt.approx.f32 %0, %1;" : "=f"(r) : "f"(x)); return r;
}
__device__ __forceinline__ void ldm4(uint32_t* r, uint32_t addr) {
    asm volatile("ldmatrix.sync.aligned.m8n8.x4.shared.b16 {%0,%1,%2,%3}, [%4];"
                 : "=r"(r[0]), "=r"(r[1]), "=r"(r[2]), "=r"(r[3]) : "r"(addr));
}
__device__ __forceinline__ void mma_bf16(float* c,
                                         const uint32_t* a, uint32_t b0, uint32_t b1) {
    asm volatile("mma.sync.aligned.m16n8k16.row.col.f32.bf16.bf16.f32 "
                 "{%0,%1,%2,%3}, {%4,%5,%6,%7}, {%8,%9}, {%0,%1,%2,%3};"
                 : "+f"(c[0]), "+f"(c[1]), "+f"(c[2]), "+f"(c[3])
                 : "r"(a[0]), "r"(a[1]), "r"(a[2]), "r"(a[3]), "r"(b0), "r"(b1));
}
__device__ __forceinline__ void cp16(uint32_t dst, const void* src) {
    asm volatile("cp.async.cg.shared.global [%0], [%1], 16;" :: "r"(dst), "l"(src));
}
__device__ __forceinline__ void cp16z(uint32_t dst, const void* src, int nb) {
    asm volatile("cp.async.cg.shared.global [%0], [%1], 16, %2;" :: "r"(dst), "l"(src), "r"(nb));
}

// ---------------- prep: z-norm shapelets -> padded bf16; init out ----------------
__global__ void prep_kernel(const float* __restrict__ sh, float* __restrict__ out) {
    int c = blockIdx.x;
    int wid = threadIdx.x >> 5, lane = threadIdx.x & 31;
    int k = blockIdx.y * 32 + wid;
    const float* p = sh + ((size_t)c * K_ + k) * S_;

    float a = p[lane], b = p[lane + 32];
    float s = a + b;
#pragma unroll
    for (int o = 16; o > 0; o >>= 1) s += __shfl_xor_sync(0xffffffffu, s, o);
    float mu = s * (1.0f / S_);
    float da = a - mu, db = b - mu;
    float v = da * da + db * db;
#pragma unroll
    for (int o = 16; o > 0; o >>= 1) v += __shfl_xor_sync(0xffffffffu, v, o);
    float inv = rsqrtf(v * (1.0f / S_));

    __nv_bfloat16* row = &g_shb[c][(size_t)k * PAD];
    row[lane]      = __float2bfloat16_rn(da * inv);
    row[lane + 32] = __float2bfloat16_rn(db * inv);

    if (c == 0) {
        int i = blockIdx.y * 1024 + threadIdx.x;
        out[i] = CUDART_INF_F;
        out[i + 4096] = CUDART_INF_F;
    }
}

// ---------------- main kernel ----------------
// 256 threads (8 warps), tile 64w x 128k. Warp: wr=w&1 (rows 32wr..), kc=w>>1 (cols 32kc..).
__global__ void __launch_bounds__(256, 2)
min_dist_kernel(const float* __restrict__ x, float* __restrict__ out) {
    extern __shared__ __align__(16) char smem[];
    const int tid = threadIdx.x, w = tid >> 5, lane = tid & 31;
    const int wr = w & 1, kc = w >> 1;
    const int g = lane >> 2, q = lane & 3;
    const int n = blockIdx.y, wbase = blockIdx.x * WT;
    const float* xrow_base = x + (size_t)n * C_ * L_;

    int* s_min = (int*)(smem + SM_MIN);

    float ds[32];
#pragma unroll
    for (int i = 0; i < 32; i++) ds[i] = 0.f;

    // ---- cp.async staging of B tile + x strip for channel c into buffer buf ----
    auto stage = [&](int c, int buf) {
        uint32_t bdst = smem_u32(smem + buf * BUFSZ + O_B);
        const char* bsrc = (const char*)&g_shb[c][0];
#pragma unroll
        for (int i = 0; i < 5; i++) {
            int idx = tid + i * 256;
            if (idx < (K_ * PAD * 2) / 16) cp16(bdst + idx * 16, bsrc + (size_t)idx * 16);
        }
        if (tid < 32) {
            int gi = wbase + tid * 4;
            int nb = (L_ - gi) * 4;
            nb = nb < 0 ? 0 : (nb > 16 ? 16 : nb);
            const float* src = (nb > 0) ? (xrow_base + (size_t)c * L_ + gi) : xrow_base;
            cp16z(smem_u32(smem + buf * BUFSZ + O_STRIP) + tid * 16, src, nb);
        }
        asm volatile("cp.async.commit_group;" ::: "memory");
    };

    // ---- build Toeplitz A tile (bf16) + per-window sqx ----
    auto build = [&](int buf) {
        const float* strip = (const float*)(smem + buf * BUFSZ + O_STRIP);
        int row = tid >> 2, p = (tid & 3) * 16;
        const float* src = &strip[row];
        __nv_bfloat162* arow = (__nv_bfloat162*)(smem + buf * BUFSZ + O_A
                                                 + (size_t)row * (PAD * 2) + p * 2);
#pragma unroll
        for (int j = 0; j < 8; j++)
            arow[j] = __floats2bfloat162_rn(src[p + 2 * j], src[p + 2 * j + 1]);
        float a = 0.f;
#pragma unroll
        for (int i = 0; i < 16; i++) { float vv = src[p + i]; a = fmaf(vv, vv, a); }
        a += __shfl_xor_sync(0xffffffffu, a, 1);
        a += __shfl_xor_sync(0xffffffffu, a, 2);
        if ((tid & 3) == 0) ((float*)(smem + buf * BUFSZ + O_SQX))[row] = a;
    };

    // ---- per-channel compute: m32n32 warp tile ----
    auto compute = [&](int buf) {
        const float* sqx = (const float*)(smem + buf * BUFSZ + O_SQX);
        uint32_t abase = smem_u32(smem + buf * BUFSZ + O_A)
                       + (uint32_t)(wr * 32 + (lane & 15)) * (PAD * 2) + (lane >> 4) * 16;
        uint32_t bbase = smem_u32(smem + buf * BUFSZ + O_B)
                       + (uint32_t)(kc * 32 + (lane & 15)) * (PAD * 2) + (lane >> 4) * 16;

        uint32_t af[2][4][4];
#pragma unroll
        for (int mi = 0; mi < 2; mi++)
#pragma unroll
            for (int kk = 0; kk < 4; kk++)
                ldm4(af[mi][kk], abase + (uint32_t)mi * 16 * (PAD * 2) + kk * 32);

        float t[2][2];   // [mi][rowhalf]: sqx + S (sqs of z-normed == S exactly)
#pragma unroll
        for (int mi = 0; mi < 2; mi++) {
            t[mi][0] = sqx[wr * 32 + mi * 16 + g]     + (float)S_;
            t[mi][1] = sqx[wr * 32 + mi * 16 + g + 8] + (float)S_;
        }

#pragma unroll
        for (int nt = 0; nt < 2; nt++) {
            uint32_t bf[4][4];
#pragma unroll
            for (int kk = 0; kk < 4; kk++)
                ldm4(bf[kk], bbase + (uint32_t)nt * 16 * (PAD * 2) + kk * 32);
            float cc[16];
#pragma unroll
            for (int e = 0; e < 16; e++) cc[e] = 0.f;
#pragma unroll
            for (int kk = 0; kk < 4; kk++)
#pragma unroll
                for (int mi = 0; mi < 2; mi++) {
                    mma_bf16(&cc[mi * 8],     af[mi][kk], bf[kk][0], bf[kk][2]);
                    mma_bf16(&cc[mi * 8 + 4], af[mi][kk], bf[kk][1], bf[kk][3]);
                }
#pragma unroll
            for (int mi = 0; mi < 2; mi++)
#pragma unroll
                for (int h = 0; h < 2; h++)
#pragma unroll
                    for (int e = 0; e < 4; e++) {
                        float d2 = fmaf(-2.f, cc[mi * 8 + h * 4 + e], t[mi][e >> 1]);
                        ds[nt * 16 + mi * 8 + h * 4 + e] += fast_sqrt(fmaxf(d2, 1e-12f));
                    }
        }
    };

    // ---- pipelined channel loop ----
    stage(0, 0);
    for (int c = 0; c < C_; c++) {
        const int buf = c & 1;
        asm volatile("cp.async.wait_group 0;" ::: "memory");
        __syncthreads();
        if (c + 1 < C_) stage(c + 1, buf ^ 1);   // lands under build+compute
        build(buf);
        __syncthreads();
        compute(buf);
    }

    // ---- min over windows ----
    if (tid < K_) s_min[tid] = 0x7F800000;
    __syncthreads();

    bool v[2][2];
#pragma unroll
    for (int mi = 0; mi < 2; mi++)
#pragma unroll
        for (int hh = 0; hh < 2; hh++)
            v[mi][hh] = (wbase + wr * 32 + mi * 16 + g + hh * 8) < W_;

#pragma unroll
    for (int nt = 0; nt < 2; nt++)
#pragma unroll
        for (int h = 0; h < 2; h++)
#pragma unroll
            for (int j = 0; j < 2; j++) {
                float m = CUDART_INF_F;
#pragma unroll
                for (int mi = 0; mi < 2; mi++)
#pragma unroll
                    for (int hh = 0; hh < 2; hh++) {
                        float val = v[mi][hh] ? ds[nt * 16 + mi * 8 + h * 4 + hh * 2 + j]
                                              : CUDART_INF_F;
                        m = fminf(m, val);
                    }
#pragma unroll
                for (int o = 4; o < 32; o <<= 1) m = fminf(m, __shfl_xor_sync(0xffffffffu, m, o));
                if (g == 0) {
                    int col = kc * 32 + nt * 16 + h * 8 + q * 2 + j;
                    atomicMin(&s_min[col], __float_as_int(m));
                }
            }
    __syncthreads();
    if (tid < K_) atomicMin((int*)&out[(size_t)n * K_ + tid], s_min[tid]);
}

// ---------------- launch ----------------
extern "C" void kernel_launch(void* const* d_in, const int* in_sizes, int n_in,
                              void* d_out, int out_size) {
    const float* x  = (const float*)d_in[0];   // (64, 8, 2048)
    const float* sh = (const float*)d_in[1];   // (8, 128, 64)
    float* out = (float*)d_out;                // (64, 1, 128)

    cudaFuncSetAttribute(min_dist_kernel, cudaFuncAttributeMaxDynamicSharedMemorySize, SM_TOTAL);

    prep_kernel<<<dim3(C_, 4), 1024>>>(sh, out);
    min_dist_kernel<<<dim3(NWT, N_), 256, SM_TOTAL>>>(x, out);
}

// round 6
// speedup vs baseline: 1.0767x; 1.0767x over previous
#include <cuda_runtime.h>
#include <cuda_bf16.h>
#include <cstdint>
#include <math_constants.h>

#define N_  64
#define C_  8
#define L_  2048
#define S_  64
#define K_  128
#define W_  (L_ - S_ + 1)          /* 1985 */
#define WT  128                    /* windows per block */
#define NWT ((W_ + WT - 1) / WT)   /* 16 */
#define PAD 72                     /* B row pitch in bf16 (144B): conflict-free ldmatrix */
#define APITCH 48                  /* A Toeplitz band pitch bytes (16B-aligned, 12-bank step) */
#define AROWS 176                  /* Toeplitz band rows needed: 96 + 64 + 16 */

// ---- dynamic smem layout (bytes, per buffer) ----
#define O_B      0                 /* 18432: B tile (128k x 64s bf16, padded)  */
#define O_A      18432             /* 8448:  A Toeplitz band (176 x 16 bf16)   */
#define O_STRIP  26880             /* 768:   192 f32                           */
#define O_SQX    27648             /* 512:   128 f32                           */
#define BUFSZ    28160
#define SM_MIN   56320             /* 128 int */
#define SM_TOTAL 56832

// ---------------- device scratch ----------------
__device__ __align__(16) __nv_bfloat16 g_shb[C_][K_ * PAD]; // z-normed shapelets, padded rows

// ---------------- helpers ----------------
__device__ __forceinline__ uint32_t smem_u32(const void* p) {
    uint32_t a;
    asm("{ .reg .u64 t; cvta.to.shared.u64 t, %1; cvt.u32.u64 %0, t; }" : "=r"(a) : "l"(p));
    return a;
}
__device__ __forceinline__ float fast_sqrt(float x) {
    float r; asm("sqrt.approx.f32 %0, %1;" : "=f"(r) : "f"(x)); return r;
}
__device__ __forceinline__ void ldm4(uint32_t* r, uint32_t addr) {
    asm volatile("ldmatrix.sync.aligned.m8n8.x4.shared.b16 {%0,%1,%2,%3}, [%4];"
                 : "=r"(r[0]), "=r"(r[1]), "=r"(r[2]), "=r"(r[3]) : "r"(addr));
}
__device__ __forceinline__ void mma_bf16(float* c,
                                         const uint32_t* a, uint32_t b0, uint32_t b1) {
    asm volatile("mma.sync.aligned.m16n8k16.row.col.f32.bf16.bf16.f32 "
                 "{%0,%1,%2,%3}, {%4,%5,%6,%7}, {%8,%9}, {%0,%1,%2,%3};"
                 : "+f"(c[0]), "+f"(c[1]), "+f"(c[2]), "+f"(c[3])
                 : "r"(a[0]), "r"(a[1]), "r"(a[2]), "r"(a[3]), "r"(b0), "r"(b1));
}
__device__ __forceinline__ void cp16(uint32_t dst, const void* src) {
    asm volatile("cp.async.cg.shared.global [%0], [%1], 16;" :: "r"(dst), "l"(src));
}
__device__ __forceinline__ void cp16z(uint32_t dst, const void* src, int nb) {
    asm volatile("cp.async.cg.shared.global [%0], [%1], 16, %2;" :: "r"(dst), "l"(src), "r"(nb));
}

// ---------------- prep: z-norm shapelets -> padded bf16; init out ----------------
__global__ void prep_kernel(const float* __restrict__ sh, float* __restrict__ out) {
    int c = blockIdx.x;
    int wid = threadIdx.x >> 5, lane = threadIdx.x & 31;
    int k = blockIdx.y * 32 + wid;
    const float* p = sh + ((size_t)c * K_ + k) * S_;

    float a = p[lane], b = p[lane + 32];
    float s = a + b;
#pragma unroll
    for (int o = 16; o > 0; o >>= 1) s += __shfl_xor_sync(0xffffffffu, s, o);
    float mu = s * (1.0f / S_);
    float da = a - mu, db = b - mu;
    float v = da * da + db * db;
#pragma unroll
    for (int o = 16; o > 0; o >>= 1) v += __shfl_xor_sync(0xffffffffu, v, o);
    float inv = rsqrtf(v * (1.0f / S_));

    __nv_bfloat16* row = &g_shb[c][(size_t)k * PAD];
    row[lane]      = __float2bfloat16_rn(da * inv);
    row[lane + 32] = __float2bfloat16_rn(db * inv);

    if (c == 0) {
        int i = blockIdx.y * 1024 + threadIdx.x;
        out[i] = CUDART_INF_F;
        out[i + 4096] = CUDART_INF_F;
    }
}

// ---------------- main kernel ----------------
// 512 threads (16 warps), tile 128w x 128k. Warp: wr=w&3 (rows 32wr..), kc=w>>2 (cols 32kc..).
__global__ void __launch_bounds__(512, 1)
min_dist_kernel(const float* __restrict__ x, float* __restrict__ out) {
    extern __shared__ __align__(16) char smem[];
    const int tid = threadIdx.x, w = tid >> 5, lane = tid & 31;
    const int wr = w & 3, kc = w >> 2;
    const int g = lane >> 2, q = lane & 3;
    const int n = blockIdx.y, wbase = blockIdx.x * WT;
    const float* xrow_base = x + (size_t)n * C_ * L_;

    int* s_min = (int*)(smem + SM_MIN);

    float ds[32];
#pragma unroll
    for (int i = 0; i < 32; i++) ds[i] = 0.f;

    // ---- cp.async staging: B tile + x strip for channel c -> buffer buf ----
    auto stage = [&](int c, int buf) {
        uint32_t bdst = smem_u32(smem + buf * BUFSZ + O_B);
        const char* bsrc = (const char*)&g_shb[c][0];
#pragma unroll
        for (int i = 0; i < 3; i++) {
            int idx = tid + i * 512;
            if (idx < (K_ * PAD * 2) / 16) cp16(bdst + idx * 16, bsrc + (size_t)idx * 16);
        }
        if (tid < 48) {           // 192 floats
            int gi = wbase + tid * 4;
            int nb = (L_ - gi) * 4;
            nb = nb < 0 ? 0 : (nb > 16 ? 16 : nb);
            const float* src = (nb > 0) ? (xrow_base + (size_t)c * L_ + gi) : xrow_base;
            cp16z(smem_u32(smem + buf * BUFSZ + O_STRIP) + tid * 16, src, nb);
        }
        asm volatile("cp.async.commit_group;" ::: "memory");
    };

    // ---- build Toeplitz band A[176 x 16] (bf16, pitch 48B) + per-window sqx ----
    auto build = [&](int buf) {
        const float* strip = (const float*)(smem + buf * BUFSZ + O_STRIP);
        char* abase = smem + buf * BUFSZ + O_A;
        // 176 rows x 8 bf16x2 = 1408 pairs
#pragma unroll
        for (int i = 0; i < 3; i++) {
            int idx = tid + i * 512;
            if (idx < AROWS * 8) {
                int row = idx >> 3, j = idx & 7;
                int s0 = row + 2 * j;   // max 175 + 14 = 189 < 192
                *(__nv_bfloat162*)(abase + row * APITCH + j * 4) =
                    __floats2bfloat162_rn(strip[s0], strip[s0 + 1]);
            }
        }
        // sqx: 4 threads per window
        int row = tid >> 2, p = (tid & 3) * 16;
        const float* src = &strip[row];
        float a = 0.f;
#pragma unroll
        for (int i = 0; i < 16; i++) { float vv = src[p + i]; a = fmaf(vv, vv, a); }
        a += __shfl_xor_sync(0xffffffffu, a, 1);
        a += __shfl_xor_sync(0xffffffffu, a, 2);
        if ((tid & 3) == 0) ((float*)(smem + buf * BUFSZ + O_SQX))[row] = a;
    };

    // ---- per-channel compute: m32n32 warp tile, diagonal A-fragment sharing ----
    auto compute = [&](int buf) {
        const float* sqx = (const float*)(smem + buf * BUFSZ + O_SQX);
        // A frag for diagonal d: rows wr*32 + d*16 + (lane&15) of the band, 16 cols
        uint32_t abase = smem_u32(smem + buf * BUFSZ + O_A)
                       + (uint32_t)(wr * 32 + (lane & 15)) * APITCH + (lane >> 4) * 16;
        uint32_t bbase = smem_u32(smem + buf * BUFSZ + O_B)
                       + (uint32_t)(kc * 32 + (lane & 15)) * (PAD * 2) + (lane >> 4) * 16;

        uint32_t af[5][4];            // d = mi + kk in 0..4
#pragma unroll
        for (int d = 0; d < 5; d++)
            ldm4(af[d], abase + (uint32_t)d * 16 * APITCH);

        float t[2][2];                // [mi][rowhalf]: sqx + S (sqs of z-norm == S)
#pragma unroll
        for (int mi = 0; mi < 2; mi++) {
            t[mi][0] = sqx[wr * 32 + mi * 16 + g]     + (float)S_;
            t[mi][1] = sqx[wr * 32 + mi * 16 + g + 8] + (float)S_;
        }

#pragma unroll
        for (int nt = 0; nt < 2; nt++) {
            uint32_t bf[4][4];
#pragma unroll
            for (int kk = 0; kk < 4; kk++)
                ldm4(bf[kk], bbase + (uint32_t)nt * 16 * (PAD * 2) + kk * 32);
            float cc[16];
#pragma unroll
            for (int e = 0; e < 16; e++) cc[e] = 0.f;
#pragma unroll
            for (int kk = 0; kk < 4; kk++)
#pragma unroll
                for (int mi = 0; mi < 2; mi++) {
                    mma_bf16(&cc[mi * 8],     af[mi + kk], bf[kk][0], bf[kk][2]);
                    mma_bf16(&cc[mi * 8 + 4], af[mi + kk], bf[kk][1], bf[kk][3]);
                }
#pragma unroll
            for (int mi = 0; mi < 2; mi++)
#pragma unroll
                for (int h = 0; h < 2; h++)
#pragma unroll
                    for (int e = 0; e < 4; e++) {
                        float d2 = fmaf(-2.f, cc[mi * 8 + h * 4 + e], t[mi][e >> 1]);
                        ds[nt * 16 + mi * 8 + h * 4 + e] += fast_sqrt(fmaxf(d2, 1e-12f));
                    }
        }
    };

    // ---- pipelined channel loop ----
    stage(0, 0);
    for (int c = 0; c < C_; c++) {
        const int buf = c & 1;
        asm volatile("cp.async.wait_group 0;" ::: "memory");
        __syncthreads();
        if (c + 1 < C_) stage(c + 1, buf ^ 1);   // lands under build+compute
        build(buf);
        __syncthreads();
        compute(buf);
    }

    // ---- min over windows ----
    if (tid < K_) s_min[tid] = 0x7F800000;
    __syncthreads();

    bool v[2][2];
#pragma unroll
    for (int mi = 0; mi < 2; mi++)
#pragma unroll
        for (int hh = 0; hh < 2; hh++)
            v[mi][hh] = (wbase + wr * 32 + mi * 16 + g + hh * 8) < W_;

#pragma unroll
    for (int nt = 0; nt < 2; nt++)
#pragma unroll
        for (int h = 0; h < 2; h++)
#pragma unroll
            for (int j = 0; j < 2; j++) {
                float m = CUDART_INF_F;
#pragma unroll
                for (int mi = 0; mi < 2; mi++)
#pragma unroll
                    for (int hh = 0; hh < 2; hh++) {
                        float val = v[mi][hh] ? ds[nt * 16 + mi * 8 + h * 4 + hh * 2 + j]
                                              : CUDART_INF_F;
                        m = fminf(m, val);
                    }
#pragma unroll
                for (int o = 4; o < 32; o <<= 1) m = fminf(m, __shfl_xor_sync(0xffffffffu, m, o));
                if (g == 0) {
                    int col = kc * 32 + nt * 16 + h * 8 + q * 2 + j;
                    atomicMin(&s_min[col], __float_as_int(m));
                }
            }
    __syncthreads();
    if (tid < K_) atomicMin((int*)&out[(size_t)n * K_ + tid], s_min[tid]);
}

// ---------------- launch ----------------
extern "C" void kernel_launch(void* const* d_in, const int* in_sizes, int n_in,
                              void* d_out, int out_size) {
    const float* x  = (const float*)d_in[0];   // (64, 8, 2048)
    const float* sh = (const float*)d_in[1];   // (8, 128, 64)
    float* out = (float*)d_out;                // (64, 1, 128)

    cudaFuncSetAttribute(min_dist_kernel, cudaFuncAttributeMaxDynamicSharedMemorySize, SM_TOTAL);

    prep_kernel<<<dim3(C_, 4), 1024>>>(sh, out);
    min_dist_kernel<<<dim3(NWT, N_), 512, SM_TOTAL>>>(x, out);
}

// round 7
// speedup vs baseline: 1.1391x; 1.0579x over previous
#include <cuda_runtime.h>
#include <cuda_bf16.h>
#include <cstdint>
#include <math_constants.h>

#define N_  64
#define C_  8
#define L_  2048
#define S_  64
#define K_  128
#define W_  (L_ - S_ + 1)          /* 1985 */
#define WT  128                    /* windows per block */
#define NWT ((W_ + WT - 1) / WT)   /* 16 */
#define PAD 72                     /* B row pitch in bf16 (144B): conflict-free ldmatrix */
#define APITCH 48                  /* A Toeplitz band pitch bytes */
#define AROWS 176                  /* band rows: 96 + 64 + 16 */

// ---- dynamic smem (per buffer): B(32k) 4608 | A band 8448 | strip 768 | sqx 512 ----
#define O_B      0
#define O_A      4608
#define O_STRIP  13056
#define O_SQX    13824
#define BUFSZ    14336
#define SM_MIN   28672             /* 32 int */
#define SM_TOTAL 28800

// ---------------- device scratch ----------------
__device__ __align__(16) __nv_bfloat16 g_shb[C_][K_ * PAD]; // z-normed shapelets, padded rows

// ---------------- helpers ----------------
__device__ __forceinline__ uint32_t smem_u32(const void* p) {
    uint32_t a;
    asm("{ .reg .u64 t; cvta.to.shared.u64 t, %1; cvt.u32.u64 %0, t; }" : "=r"(a) : "l"(p));
    return a;
}
__device__ __forceinline__ float fast_sqrt(float x) {
    float r; asm("sqrt.approx.f32 %0, %1;" : "=f"(r) : "f"(x)); return r;
}
__device__ __forceinline__ void ldm4(uint32_t* r, uint32_t addr) {
    asm volatile("ldmatrix.sync.aligned.m8n8.x4.shared.b16 {%0,%1,%2,%3}, [%4];"
                 : "=r"(r[0]), "=r"(r[1]), "=r"(r[2]), "=r"(r[3]) : "r"(addr));
}
__device__ __forceinline__ void mma_bf16(float* c,
                                         const uint32_t* a, uint32_t b0, uint32_t b1) {
    asm volatile("mma.sync.aligned.m16n8k16.row.col.f32.bf16.bf16.f32 "
                 "{%0,%1,%2,%3}, {%4,%5,%6,%7}, {%8,%9}, {%0,%1,%2,%3};"
                 : "+f"(c[0]), "+f"(c[1]), "+f"(c[2]), "+f"(c[3])
                 : "r"(a[0]), "r"(a[1]), "r"(a[2]), "r"(a[3]), "r"(b0), "r"(b1));
}
__device__ __forceinline__ void cp16(uint32_t dst, const void* src) {
    asm volatile("cp.async.cg.shared.global [%0], [%1], 16;" :: "r"(dst), "l"(src));
}
__device__ __forceinline__ void cp16z(uint32_t dst, const void* src, int nb) {
    asm volatile("cp.async.cg.shared.global [%0], [%1], 16, %2;" :: "r"(dst), "l"(src), "r"(nb));
}

// ---------------- prep: z-norm shapelets -> padded bf16; init out ----------------
__global__ void prep_kernel(const float* __restrict__ sh, float* __restrict__ out) {
    int c = blockIdx.x;
    int wid = threadIdx.x >> 5, lane = threadIdx.x & 31;
    int k = blockIdx.y * 32 + wid;
    const float* p = sh + ((size_t)c * K_ + k) * S_;

    float a = p[lane], b = p[lane + 32];
    float s = a + b;
#pragma unroll
    for (int o = 16; o > 0; o >>= 1) s += __shfl_xor_sync(0xffffffffu, s, o);
    float mu = s * (1.0f / S_);
    float da = a - mu, db = b - mu;
    float v = da * da + db * db;
#pragma unroll
    for (int o = 16; o > 0; o >>= 1) v += __shfl_xor_sync(0xffffffffu, v, o);
    float inv = rsqrtf(v * (1.0f / S_));

    __nv_bfloat16* row = &g_shb[c][(size_t)k * PAD];
    row[lane]      = __float2bfloat16_rn(da * inv);
    row[lane + 32] = __float2bfloat16_rn(db * inv);

    if (c == 0) {
        int i = blockIdx.y * 1024 + threadIdx.x;
        out[i] = CUDART_INF_F;
        out[i + 4096] = CUDART_INF_F;
    }
}

// ---------------- main kernel ----------------
// 128 threads (4 warps). CTA tile: 128w x 32k (k-quarter = blockIdx.y).
// Warp wr = w (0..3): rows 32*wr..32*wr+31, all 32 cols.
__global__ void __launch_bounds__(128, 4)
min_dist_kernel(const float* __restrict__ x, float* __restrict__ out) {
    extern __shared__ __align__(16) char smem[];
    const int tid = threadIdx.x, wr = tid >> 5, lane = tid & 31;
    const int g = lane >> 2, q = lane & 3;
    const int kq = blockIdx.y, n = blockIdx.z, wbase = blockIdx.x * WT;
    const float* xrow_base = x + (size_t)n * C_ * L_;

    int* s_min = (int*)(smem + SM_MIN);

    float ds[32];
#pragma unroll
    for (int i = 0; i < 32; i++) ds[i] = 0.f;

    // ---- cp.async staging: this k-quarter's B rows + x strip -> buffer buf ----
    auto stage = [&](int c, int buf) {
        uint32_t bdst = smem_u32(smem + buf * BUFSZ + O_B);
        const char* bsrc = (const char*)&g_shb[c][(size_t)kq * 32 * PAD];
#pragma unroll
        for (int i = 0; i < 3; i++) {
            int idx = tid + i * 128;
            if (idx < (32 * PAD * 2) / 16) cp16(bdst + idx * 16, bsrc + (size_t)idx * 16);
        }
        if (tid < 48) {           // 192 floats
            int gi = wbase + tid * 4;
            int nb = (L_ - gi) * 4;
            nb = nb < 0 ? 0 : (nb > 16 ? 16 : nb);
            const float* src = (nb > 0) ? (xrow_base + (size_t)c * L_ + gi) : xrow_base;
            cp16z(smem_u32(smem + buf * BUFSZ + O_STRIP) + tid * 16, src, nb);
        }
        asm volatile("cp.async.commit_group;" ::: "memory");
    };

    // ---- build Toeplitz band A[176 x 16] + per-window sqx ----
    auto build = [&](int buf) {
        const float* strip = (const float*)(smem + buf * BUFSZ + O_STRIP);
        char* abase = smem + buf * BUFSZ + O_A;
        // 1408 bf16x2 pairs, 11 per thread
#pragma unroll
        for (int i = 0; i < 11; i++) {
            int idx = tid + i * 128;
            int row = idx >> 3, j = idx & 7;
            int s0 = row + 2 * j;
            *(__nv_bfloat162*)(abase + row * APITCH + j * 4) =
                __floats2bfloat162_rn(strip[s0], strip[s0 + 1]);
        }
        // sqx: 1 thread per window, 4 parallel partials
        {
            const float* src = &strip[tid];
            float a0 = 0.f, a1 = 0.f, a2 = 0.f, a3 = 0.f;
#pragma unroll
            for (int i = 0; i < 16; i++) {
                float v0 = src[4 * i],     v1 = src[4 * i + 1];
                float v2 = src[4 * i + 2], v3 = src[4 * i + 3];
                a0 = fmaf(v0, v0, a0); a1 = fmaf(v1, v1, a1);
                a2 = fmaf(v2, v2, a2); a3 = fmaf(v3, v3, a3);
            }
            ((float*)(smem + buf * BUFSZ + O_SQX))[tid] = (a0 + a1) + (a2 + a3);
        }
    };

    // ---- per-channel compute: m32n32 warp tile, diagonal A sharing ----
    auto compute = [&](int buf) {
        const float* sqx = (const float*)(smem + buf * BUFSZ + O_SQX);
        uint32_t abase = smem_u32(smem + buf * BUFSZ + O_A)
                       + (uint32_t)(wr * 32 + (lane & 15)) * APITCH + (lane >> 4) * 16;
        uint32_t bbase = smem_u32(smem + buf * BUFSZ + O_B)
                       + (uint32_t)(lane & 15) * (PAD * 2) + (lane >> 4) * 16;

        uint32_t af[5][4];            // diagonal d = mi + kk, d in 0..4
#pragma unroll
        for (int d = 0; d < 5; d++)
            ldm4(af[d], abase + (uint32_t)d * 16 * APITCH);

        float t[2][2];                // [mi][rowhalf]: sqx + S (sqs of z-norm == S)
#pragma unroll
        for (int mi = 0; mi < 2; mi++) {
            t[mi][0] = sqx[wr * 32 + mi * 16 + g]     + (float)S_;
            t[mi][1] = sqx[wr * 32 + mi * 16 + g + 8] + (float)S_;
        }

#pragma unroll
        for (int nt = 0; nt < 2; nt++) {
            uint32_t bf[4][4];
#pragma unroll
            for (int kk = 0; kk < 4; kk++)
                ldm4(bf[kk], bbase + (uint32_t)nt * 16 * (PAD * 2) + kk * 32);
            float cc[16];
#pragma unroll
            for (int e = 0; e < 16; e++) cc[e] = 0.f;
#pragma unroll
            for (int kk = 0; kk < 4; kk++)
#pragma unroll
                for (int mi = 0; mi < 2; mi++) {
                    mma_bf16(&cc[mi * 8],     af[mi + kk], bf[kk][0], bf[kk][2]);
                    mma_bf16(&cc[mi * 8 + 4], af[mi + kk], bf[kk][1], bf[kk][3]);
                }
#pragma unroll
            for (int mi = 0; mi < 2; mi++)
#pragma unroll
                for (int h = 0; h < 2; h++)
#pragma unroll
                    for (int e = 0; e < 4; e++) {
                        float d2 = fmaf(-2.f, cc[mi * 8 + h * 4 + e], t[mi][e >> 1]);
                        ds[nt * 16 + mi * 8 + h * 4 + e] += fast_sqrt(fmaxf(d2, 1e-12f));
                    }
        }
    };

    // ---- pipelined channel loop ----
    stage(0, 0);
    for (int c = 0; c < C_; c++) {
        const int buf = c & 1;
        asm volatile("cp.async.wait_group 0;" ::: "memory");
        __syncthreads();
        if (c + 1 < C_) stage(c + 1, buf ^ 1);   // lands under build+compute
        build(buf);
        __syncthreads();
        compute(buf);
    }

    // ---- min over windows (32 cols for this k-quarter) ----
    if (tid < 32) s_min[tid] = 0x7F800000;
    __syncthreads();

    bool v[2][2];
#pragma unroll
    for (int mi = 0; mi < 2; mi++)
#pragma unroll
        for (int hh = 0; hh < 2; hh++)
            v[mi][hh] = (wbase + wr * 32 + mi * 16 + g + hh * 8) < W_;

#pragma unroll
    for (int nt = 0; nt < 2; nt++)
#pragma unroll
        for (int h = 0; h < 2; h++)
#pragma unroll
            for (int j = 0; j < 2; j++) {
                float m = CUDART_INF_F;
#pragma unroll
                for (int mi = 0; mi < 2; mi++)
#pragma unroll
                    for (int hh = 0; hh < 2; hh++) {
                        float val = v[mi][hh] ? ds[nt * 16 + mi * 8 + h * 4 + hh * 2 + j]
                                              : CUDART_INF_F;
                        m = fminf(m, val);
                    }
#pragma unroll
                for (int o = 4; o < 32; o <<= 1) m = fminf(m, __shfl_xor_sync(0xffffffffu, m, o));
                if (g == 0) {
                    int col = nt * 16 + h * 8 + q * 2 + j;
                    atomicMin(&s_min[col], __float_as_int(m));
                }
            }
    __syncthreads();
    if (tid < 32) atomicMin((int*)&out[(size_t)n * K_ + kq * 32 + tid], s_min[tid]);
}

// ---------------- launch ----------------
extern "C" void kernel_launch(void* const* d_in, const int* in_sizes, int n_in,
                              void* d_out, int out_size) {
    const float* x  = (const float*)d_in[0];   // (64, 8, 2048)
    const float* sh = (const float*)d_in[1];   // (8, 128, 64)
    float* out = (float*)d_out;                // (64, 1, 128)

    cudaFuncSetAttribute(min_dist_kernel, cudaFuncAttributeMaxDynamicSharedMemorySize, SM_TOTAL);

    prep_kernel<<<dim3(C_, 4), 1024>>>(sh, out);
    min_dist_kernel<<<dim3(NWT, 4, N_), 128, SM_TOTAL>>>(x, out);
}

// round 8
// speedup vs baseline: 1.3636x; 1.1971x over previous
#include <cuda_runtime.h>
#include <cuda_bf16.h>
#include <cstdint>
#include <math_constants.h>

#define N_  64
#define C_  8
#define L_  2048
#define S_  64
#define K_  128
#define W_  (L_ - S_ + 1)          /* 1985 */
#define WT  128                    /* windows per block */
#define NWT ((W_ + WT - 1) / WT)   /* 16 */
#define PAD 72                     /* B row pitch in bf16 (144B): conflict-free ldmatrix */
#define APITCH 48                  /* band pitch bytes (16B-aligned, 12-bank step) */
#define AROWS 176                  /* band rows staged per tile */
#define BROWS 2112                 /* global band rows per (n,c), zero-padded */

// ---- dynamic smem (per buffer): band 8448 | B(32k) 4608 | sqx 512 ----
#define O_A      0
#define O_B      8448
#define O_SQX    13056
#define BUFSZ    13568
#define SM_MIN   27136             /* 32 int */
#define SM_TOTAL 27264

// ---------------- device scratch ----------------
__device__ __align__(16) __nv_bfloat16 g_shb[C_][K_ * PAD];            // z-normed shapelets
__device__ __align__(16) __nv_bfloat16 g_band[N_][C_][BROWS * 24];     // Toeplitz band, pitch 48B
__device__ __align__(16) float         g_sqx[N_][C_][2048];            // window sum-of-squares

// ---------------- helpers ----------------
__device__ __forceinline__ uint32_t smem_u32(const void* p) {
    uint32_t a;
    asm("{ .reg .u64 t; cvta.to.shared.u64 t, %1; cvt.u32.u64 %0, t; }" : "=r"(a) : "l"(p));
    return a;
}
__device__ __forceinline__ float fast_sqrt(float x) {
    float r; asm("sqrt.approx.f32 %0, %1;" : "=f"(r) : "f"(x)); return r;
}
__device__ __forceinline__ void ldm4(uint32_t* r, uint32_t addr) {
    asm volatile("ldmatrix.sync.aligned.m8n8.x4.shared.b16 {%0,%1,%2,%3}, [%4];"
                 : "=r"(r[0]), "=r"(r[1]), "=r"(r[2]), "=r"(r[3]) : "r"(addr));
}
__device__ __forceinline__ void mma_bf16(float* c,
                                         const uint32_t* a, uint32_t b0, uint32_t b1) {
    asm volatile("mma.sync.aligned.m16n8k16.row.col.f32.bf16.bf16.f32 "
                 "{%0,%1,%2,%3}, {%4,%5,%6,%7}, {%8,%9}, {%0,%1,%2,%3};"
                 : "+f"(c[0]), "+f"(c[1]), "+f"(c[2]), "+f"(c[3])
                 : "r"(a[0]), "r"(a[1]), "r"(a[2]), "r"(a[3]), "r"(b0), "r"(b1));
}
__device__ __forceinline__ void cp16(uint32_t dst, const void* src) {
    asm volatile("cp.async.cg.shared.global [%0], [%1], 16;" :: "r"(dst), "l"(src));
}

// ---------------- merged prep ----------------
// blocks 0..511   : band + sqx for (n = b>>3, c = b&7), 256 threads
// blocks 512..639 : shapelet z-norm, block b: c = (b-512)>>4, kg = (b-512)&15 (8 shapelets)
//                   c==0 blocks also init out
__global__ void prep_kernel(const float* __restrict__ x, const float* __restrict__ sh,
                            float* __restrict__ out) {
    const int b = blockIdx.x, tid = threadIdx.x;
    if (b < 512) {
        const int n = b >> 3, c = b & 7;
        __shared__ float sx[L_];
        const float* xr = x + ((size_t)n * C_ + c) * L_;
        for (int i = tid; i < L_; i += 256) sx[i] = xr[i];
        __syncthreads();

        __nv_bfloat16* band = &g_band[n][c][0];
        for (int idx = tid; idx < BROWS * 8; idx += 256) {
            int row = idx >> 3, j = idx & 7;
            int s0 = row + 2 * j;
            float f0 = (s0 < L_)     ? sx[s0]     : 0.f;
            float f1 = (s0 + 1 < L_) ? sx[s0 + 1] : 0.f;
            *(__nv_bfloat162*)((char*)band + (size_t)row * APITCH + j * 4) =
                __floats2bfloat162_rn(f0, f1);
        }
        for (int w = tid; w < 2048; w += 256) {
            float a0 = 0.f, a1 = 0.f, a2 = 0.f, a3 = 0.f;
            if (w < W_) {
                const float* src = &sx[w];
#pragma unroll
                for (int i = 0; i < 16; i++) {
                    float v0 = src[4 * i],     v1 = src[4 * i + 1];
                    float v2 = src[4 * i + 2], v3 = src[4 * i + 3];
                    a0 = fmaf(v0, v0, a0); a1 = fmaf(v1, v1, a1);
                    a2 = fmaf(v2, v2, a2); a3 = fmaf(v3, v3, a3);
                }
            }
            g_sqx[n][c][w] = (a0 + a1) + (a2 + a3);
        }
    } else {
        const int bb = b - 512;
        const int c = bb >> 4, kg = bb & 15;
        const int wid = tid >> 5, lane = tid & 31;
        const int k = kg * 8 + wid;
        const float* p = sh + ((size_t)c * K_ + k) * S_;

        float a = p[lane], bv = p[lane + 32];
        float s = a + bv;
#pragma unroll
        for (int o = 16; o > 0; o >>= 1) s += __shfl_xor_sync(0xffffffffu, s, o);
        float mu = s * (1.0f / S_);
        float da = a - mu, db = bv - mu;
        float v = da * da + db * db;
#pragma unroll
        for (int o = 16; o > 0; o >>= 1) v += __shfl_xor_sync(0xffffffffu, v, o);
        float inv = rsqrtf(v * (1.0f / S_));

        __nv_bfloat16* row = &g_shb[c][(size_t)k * PAD];
        row[lane]      = __float2bfloat16_rn(da * inv);
        row[lane + 32] = __float2bfloat16_rn(db * inv);

        if (c == 0) {   // 16 blocks x 256 thr = 4096 -> 2 outputs each
            int i = kg * 256 + tid;
            out[i] = CUDART_INF_F;
            out[i + 4096] = CUDART_INF_F;
        }
    }
}

// ---------------- main kernel ----------------
// 128 threads (4 warps). CTA tile: 128w x 32k (k-quarter = blockIdx.y).
__global__ void __launch_bounds__(128, 4)
min_dist_kernel(const float* __restrict__ x, float* __restrict__ out) {
    extern __shared__ __align__(16) char smem[];
    const int tid = threadIdx.x, wr = tid >> 5, lane = tid & 31;
    const int g = lane >> 2, q = lane & 3;
    const int kq = blockIdx.y, n = blockIdx.z, wbase = blockIdx.x * WT;

    int* s_min = (int*)(smem + SM_MIN);

    float ds[32];
#pragma unroll
    for (int i = 0; i < 32; i++) ds[i] = 0.f;

    // ---- cp.async staging: band slice + B quarter + sqx slice -> buffer buf ----
    auto stage = [&](int c, int buf) {
        uint32_t adst = smem_u32(smem + buf * BUFSZ + O_A);
        const char* asrc = (const char*)&g_band[n][c][0] + (size_t)wbase * APITCH;
#pragma unroll
        for (int i = 0; i < 5; i++) {            // 528 chunks
            int idx = tid + i * 128;
            if (idx < (AROWS * APITCH) / 16) cp16(adst + idx * 16, asrc + (size_t)idx * 16);
        }
        uint32_t bdst = smem_u32(smem + buf * BUFSZ + O_B);
        const char* bsrc = (const char*)&g_shb[c][(size_t)kq * 32 * PAD];
#pragma unroll
        for (int i = 0; i < 3; i++) {            // 288 chunks
            int idx = tid + i * 128;
            if (idx < (32 * PAD * 2) / 16) cp16(bdst + idx * 16, bsrc + (size_t)idx * 16);
        }
        if (tid < 32)                            // 128 floats
            cp16(smem_u32(smem + buf * BUFSZ + O_SQX) + tid * 16,
                 (const char*)&g_sqx[n][c][wbase] + tid * 16);
        asm volatile("cp.async.commit_group;" ::: "memory");
    };

    // ---- per-channel compute: m32n32 warp tile, diagonal A sharing ----
    auto compute = [&](int buf) {
        const float* sqx = (const float*)(smem + buf * BUFSZ + O_SQX);
        uint32_t abase = smem_u32(smem + buf * BUFSZ + O_A)
                       + (uint32_t)(wr * 32 + (lane & 15)) * APITCH + (lane >> 4) * 16;
        uint32_t bbase = smem_u32(smem + buf * BUFSZ + O_B)
                       + (uint32_t)(lane & 15) * (PAD * 2) + (lane >> 4) * 16;

        uint32_t af[5][4];            // diagonal d = mi + kk, d in 0..4
#pragma unroll
        for (int d = 0; d < 5; d++)
            ldm4(af[d], abase + (uint32_t)d * 16 * APITCH);

        float t[2][2];                // [mi][rowhalf]: sqx + S (sqs of z-norm == S)
#pragma unroll
        for (int mi = 0; mi < 2; mi++) {
            t[mi][0] = sqx[wr * 32 + mi * 16 + g]     + (float)S_;
            t[mi][1] = sqx[wr * 32 + mi * 16 + g + 8] + (float)S_;
        }

#pragma unroll
        for (int nt = 0; nt < 2; nt++) {
            uint32_t bf[4][4];
#pragma unroll
            for (int kk = 0; kk < 4; kk++)
                ldm4(bf[kk], bbase + (uint32_t)nt * 16 * (PAD * 2) + kk * 32);
            float cc[16];
#pragma unroll
            for (int e = 0; e < 16; e++) cc[e] = 0.f;
#pragma unroll
            for (int kk = 0; kk < 4; kk++)
#pragma unroll
                for (int mi = 0; mi < 2; mi++) {
                    mma_bf16(&cc[mi * 8],     af[mi + kk], bf[kk][0], bf[kk][2]);
                    mma_bf16(&cc[mi * 8 + 4], af[mi + kk], bf[kk][1], bf[kk][3]);
                }
#pragma unroll
            for (int mi = 0; mi < 2; mi++)
#pragma unroll
                for (int h = 0; h < 2; h++)
#pragma unroll
                    for (int e = 0; e < 4; e++) {
                        float d2 = fmaf(-2.f, cc[mi * 8 + h * 4 + e], t[mi][e >> 1]);
                        ds[nt * 16 + mi * 8 + h * 4 + e] += fast_sqrt(fmaxf(d2, 1e-12f));
                    }
        }
    };

    // ---- pipelined channel loop ----
    stage(0, 0);
    for (int c = 0; c < C_; c++) {
        const int buf = c & 1;
        asm volatile("cp.async.wait_group 0;" ::: "memory");
        __syncthreads();
        if (c + 1 < C_) stage(c + 1, buf ^ 1);   // lands under compute
        compute(buf);
        __syncthreads();
    }

    // ---- min over windows (32 cols for this k-quarter) ----
    if (tid < 32) s_min[tid] = 0x7F800000;
    __syncthreads();

    bool v[2][2];
#pragma unroll
    for (int mi = 0; mi < 2; mi++)
#pragma unroll
        for (int hh = 0; hh < 2; hh++)
            v[mi][hh] = (wbase + wr * 32 + mi * 16 + g + hh * 8) < W_;

#pragma unroll
    for (int nt = 0; nt < 2; nt++)
#pragma unroll
        for (int h = 0; h < 2; h++)
#pragma unroll
            for (int j = 0; j < 2; j++) {
                float m = CUDART_INF_F;
#pragma unroll
                for (int mi = 0; mi < 2; mi++)
#pragma unroll
                    for (int hh = 0; hh < 2; hh++) {
                        float val = v[mi][hh] ? ds[nt * 16 + mi * 8 + h * 4 + hh * 2 + j]
                                              : CUDART_INF_F;
                        m = fminf(m, val);
                    }
#pragma unroll
                for (int o = 4; o < 32; o <<= 1) m = fminf(m, __shfl_xor_sync(0xffffffffu, m, o));
                if (g == 0) {
                    int col = nt * 16 + h * 8 + q * 2 + j;
                    atomicMin(&s_min[col], __float_as_int(m));
                }
            }
    __syncthreads();
    if (tid < 32) atomicMin((int*)&out[(size_t)n * K_ + kq * 32 + tid], s_min[tid]);
}

// ---------------- launch ----------------
extern "C" void kernel_launch(void* const* d_in, const int* in_sizes, int n_in,
                              void* d_out, int out_size) {
    const float* x  = (const float*)d_in[0];   // (64, 8, 2048)
    const float* sh = (const float*)d_in[1];   // (8, 128, 64)
    float* out = (float*)d_out;                // (64, 1, 128)

    cudaFuncSetAttribute(min_dist_kernel, cudaFuncAttributeMaxDynamicSharedMemorySize, SM_TOTAL);

    prep_kernel<<<640, 256>>>(x, sh, out);
    min_dist_kernel<<<dim3(NWT, 4, N_), 128, SM_TOTAL>>>(x, out);
}

// round 9
// speedup vs baseline: 1.4130x; 1.0363x over previous
#include <cuda_runtime.h>
#include <cuda_bf16.h>
#include <cstdint>
#include <math_constants.h>

#define N_  64
#define C_  8
#define L_  2048
#define S_  64
#define K_  128
#define W_  (L_ - S_ + 1)          /* 1985 */
#define WT  128                    /* windows per block */
#define NWT ((W_ + WT - 1) / WT)   /* 16 */
#define PAD 72                     /* B row pitch in bf16 (144B): conflict-free ldmatrix */
#define APITCH 48                  /* band pitch bytes (16B-aligned, 12-bank step) */
#define AROWS 176                  /* band rows staged per tile */
#define BROWS 2112                 /* global band rows per (n,c), zero-padded */

// ---- dynamic smem (per buffer): band 8448 | B(32k) 4608 | sqx 512 ----
#define O_A      0
#define O_B      8448
#define O_SQX    13056
#define BUFSZ    13568
#define SM_MIN   40704             /* 32 int, after 3 buffers */
#define SM_TOTAL 40832

// ---------------- device scratch ----------------
__device__ __align__(16) __nv_bfloat16 g_shb[C_][K_ * PAD];            // z-normed shapelets
__device__ __align__(16) __nv_bfloat16 g_band[N_][C_][BROWS * 24];     // Toeplitz band, pitch 48B
__device__ __align__(16) float         g_sqx[N_][C_][2048];            // window sum-of-squares

// ---------------- helpers ----------------
__device__ __forceinline__ uint32_t smem_u32(const void* p) {
    uint32_t a;
    asm("{ .reg .u64 t; cvta.to.shared.u64 t, %1; cvt.u32.u64 %0, t; }" : "=r"(a) : "l"(p));
    return a;
}
__device__ __forceinline__ float fast_sqrt(float x) {
    float r; asm("sqrt.approx.f32 %0, %1;" : "=f"(r) : "f"(x)); return r;
}
__device__ __forceinline__ void ldm4(uint32_t* r, uint32_t addr) {
    asm volatile("ldmatrix.sync.aligned.m8n8.x4.shared.b16 {%0,%1,%2,%3}, [%4];"
                 : "=r"(r[0]), "=r"(r[1]), "=r"(r[2]), "=r"(r[3]) : "r"(addr));
}
__device__ __forceinline__ void mma_bf16(float* c,
                                         const uint32_t* a, uint32_t b0, uint32_t b1) {
    asm volatile("mma.sync.aligned.m16n8k16.row.col.f32.bf16.bf16.f32 "
                 "{%0,%1,%2,%3}, {%4,%5,%6,%7}, {%8,%9}, {%0,%1,%2,%3};"
                 : "+f"(c[0]), "+f"(c[1]), "+f"(c[2]), "+f"(c[3])
                 : "r"(a[0]), "r"(a[1]), "r"(a[2]), "r"(a[3]), "r"(b0), "r"(b1));
}
__device__ __forceinline__ void cp16(uint32_t dst, const void* src) {
    asm volatile("cp.async.cg.shared.global [%0], [%1], 16;" :: "r"(dst), "l"(src));
}
__device__ __forceinline__ uint32_t bf2u(float a, float b) {
    __nv_bfloat162 v = __floats2bfloat162_rn(a, b);
    return *(uint32_t*)&v;
}

// ---------------- merged prep (576 blocks x 512 threads) ----------------
// blocks 0..511   : band + sqx for (n = b>>3, c = b&7)
// blocks 512..575 : shapelet z-norm (c = bb>>3, k = (bb&7)*16 + wid); c==0 also init out
__global__ void prep_kernel(const float* __restrict__ x, const float* __restrict__ sh,
                            float* __restrict__ out) {
    const int b = blockIdx.x, tid = threadIdx.x;
    if (b < 512) {
        const int n = b >> 3, c = b & 7;
        __shared__ float sx[L_];
        const float4* xr4 = (const float4*)(x + ((size_t)n * C_ + c) * L_);
        ((float4*)sx)[tid] = xr4[tid];   // 512 x 16B = 2048 floats
        __syncthreads();

        // band: 2112 rows x 2 chunks of 16B, vectorized STG.128
        char* band = (char*)&g_band[n][c][0];
#pragma unroll
        for (int i = 0; i < 9; i++) {
            int idx = tid + i * 512;
            if (idx < BROWS * 2) {
                int row = idx >> 1, h = idx & 1;
                int s0 = row + 8 * h;
                float f[8];
#pragma unroll
                for (int j = 0; j < 8; j++) { int s = s0 + j; f[j] = (s < L_) ? sx[s] : 0.f; }
                uint4 v;
                v.x = bf2u(f[0], f[1]); v.y = bf2u(f[2], f[3]);
                v.z = bf2u(f[4], f[5]); v.w = bf2u(f[6], f[7]);
                *(uint4*)(band + (size_t)row * APITCH + h * 16) = v;
            }
        }
        // sqx: 4 windows per thread
#pragma unroll
        for (int it = 0; it < 4; it++) {
            int w = tid + it * 512;
            float a0 = 0.f, a1 = 0.f, a2 = 0.f, a3 = 0.f;
            if (w < W_) {
                const float* src = &sx[w];
#pragma unroll
                for (int i = 0; i < 16; i++) {
                    float v0 = src[4 * i],     v1 = src[4 * i + 1];
                    float v2 = src[4 * i + 2], v3 = src[4 * i + 3];
                    a0 = fmaf(v0, v0, a0); a1 = fmaf(v1, v1, a1);
                    a2 = fmaf(v2, v2, a2); a3 = fmaf(v3, v3, a3);
                }
            }
            g_sqx[n][c][w] = (a0 + a1) + (a2 + a3);
        }
    } else {
        const int bb = b - 512;
        const int c = bb >> 3, kg = bb & 7;
        const int wid = tid >> 5, lane = tid & 31;
        const int k = kg * 16 + wid;
        const float* p = sh + ((size_t)c * K_ + k) * S_;

        float a = p[lane], bv = p[lane + 32];
        float s = a + bv;
#pragma unroll
        for (int o = 16; o > 0; o >>= 1) s += __shfl_xor_sync(0xffffffffu, s, o);
        float mu = s * (1.0f / S_);
        float da = a - mu, db = bv - mu;
        float v = da * da + db * db;
#pragma unroll
        for (int o = 16; o > 0; o >>= 1) v += __shfl_xor_sync(0xffffffffu, v, o);
        float inv = rsqrtf(v * (1.0f / S_));

        __nv_bfloat16* row = &g_shb[c][(size_t)k * PAD];
        row[lane]      = __float2bfloat16_rn(da * inv);
        row[lane + 32] = __float2bfloat16_rn(db * inv);

        if (c == 0) {   // 8 blocks x 512 thr = 4096 -> 2 outputs each
            int i = kg * 512 + tid;
            out[i] = CUDART_INF_F;
            out[i + 4096] = CUDART_INF_F;
        }
    }
}

// ---------------- main kernel ----------------
// 128 threads (4 warps). CTA tile: 128w x 32k (k-quarter = blockIdx.y).
__global__ void __launch_bounds__(128, 4)
min_dist_kernel(const float* __restrict__ x, float* __restrict__ out) {
    extern __shared__ __align__(16) char smem[];
    const int tid = threadIdx.x, wr = tid >> 5, lane = tid & 31;
    const int g = lane >> 2, q = lane & 3;
    const int kq = blockIdx.y, n = blockIdx.z, wbase = blockIdx.x * WT;

    int* s_min = (int*)(smem + SM_MIN);

    float ds[32];
#pragma unroll
    for (int i = 0; i < 32; i++) ds[i] = 0.f;

    // ---- cp.async staging: band slice + B quarter + sqx slice -> buffer buf ----
    auto stage = [&](int c, int buf) {
        uint32_t adst = smem_u32(smem + buf * BUFSZ + O_A);
        const char* asrc = (const char*)&g_band[n][c][0] + (size_t)wbase * APITCH;
#pragma unroll
        for (int i = 0; i < 5; i++) {            // 528 chunks
            int idx = tid + i * 128;
            if (idx < (AROWS * APITCH) / 16) cp16(adst + idx * 16, asrc + (size_t)idx * 16);
        }
        uint32_t bdst = smem_u32(smem + buf * BUFSZ + O_B);
        const char* bsrc = (const char*)&g_shb[c][(size_t)kq * 32 * PAD];
#pragma unroll
        for (int i = 0; i < 3; i++) {            // 288 chunks
            int idx = tid + i * 128;
            if (idx < (32 * PAD * 2) / 16) cp16(bdst + idx * 16, bsrc + (size_t)idx * 16);
        }
        if (tid < 32)                            // 128 floats
            cp16(smem_u32(smem + buf * BUFSZ + O_SQX) + tid * 16,
                 (const char*)&g_sqx[n][c][wbase] + tid * 16);
        asm volatile("cp.async.commit_group;" ::: "memory");
    };

    // ---- per-channel compute: m32n32 warp tile, diagonal A sharing ----
    auto compute = [&](int buf) {
        const float* sqx = (const float*)(smem + buf * BUFSZ + O_SQX);
        uint32_t abase = smem_u32(smem + buf * BUFSZ + O_A)
                       + (uint32_t)(wr * 32 + (lane & 15)) * APITCH + (lane >> 4) * 16;
        uint32_t bbase = smem_u32(smem + buf * BUFSZ + O_B)
                       + (uint32_t)(lane & 15) * (PAD * 2) + (lane >> 4) * 16;

        uint32_t af[5][4];            // diagonal d = mi + kk, d in 0..4
#pragma unroll
        for (int d = 0; d < 5; d++)
            ldm4(af[d], abase + (uint32_t)d * 16 * APITCH);

        float t[2][2];                // [mi][rowhalf]: sqx + S (sqs of z-norm == S)
#pragma unroll
        for (int mi = 0; mi < 2; mi++) {
            t[mi][0] = sqx[wr * 32 + mi * 16 + g]     + (float)S_;
            t[mi][1] = sqx[wr * 32 + mi * 16 + g + 8] + (float)S_;
        }

#pragma unroll
        for (int nt = 0; nt < 2; nt++) {
            uint32_t bf[4][4];
#pragma unroll
            for (int kk = 0; kk < 4; kk++)
                ldm4(bf[kk], bbase + (uint32_t)nt * 16 * (PAD * 2) + kk * 32);
            float cc[16];
#pragma unroll
            for (int e = 0; e < 16; e++) cc[e] = 0.f;
#pragma unroll
            for (int kk = 0; kk < 4; kk++)
#pragma unroll
                for (int mi = 0; mi < 2; mi++) {
                    mma_bf16(&cc[mi * 8],     af[mi + kk], bf[kk][0], bf[kk][2]);
                    mma_bf16(&cc[mi * 8 + 4], af[mi + kk], bf[kk][1], bf[kk][3]);
                }
#pragma unroll
            for (int mi = 0; mi < 2; mi++)
#pragma unroll
                for (int h = 0; h < 2; h++)
#pragma unroll
                    for (int e = 0; e < 4; e++) {
                        float d2 = fmaf(-2.f, cc[mi * 8 + h * 4 + e], t[mi][e >> 1]);
                        ds[nt * 16 + mi * 8 + h * 4 + e] += fast_sqrt(fmaxf(d2, 1e-12f));
                    }
        }
    };

    // ---- triple-buffered channel loop: one barrier per channel ----
    stage(0, 0);
    stage(1, 1);
#pragma unroll
    for (int c = 0; c < C_; c++) {
        if (c + 2 < C_) asm volatile("cp.async.wait_group 1;" ::: "memory");
        else            asm volatile("cp.async.wait_group 0;" ::: "memory");
        __syncthreads();
        if (c + 2 < C_) stage(c + 2, (c + 2) % 3);
        compute(c % 3);
    }

    // ---- min over windows (32 cols for this k-quarter) ----
    __syncthreads();
    if (tid < 32) s_min[tid] = 0x7F800000;
    __syncthreads();

    bool v[2][2];
#pragma unroll
    for (int mi = 0; mi < 2; mi++)
#pragma unroll
        for (int hh = 0; hh < 2; hh++)
            v[mi][hh] = (wbase + wr * 32 + mi * 16 + g + hh * 8) < W_;

#pragma unroll
    for (int nt = 0; nt < 2; nt++)
#pragma unroll
        for (int h = 0; h < 2; h++)
#pragma unroll
            for (int j = 0; j < 2; j++) {
                float m = CUDART_INF_F;
#pragma unroll
                for (int mi = 0; mi < 2; mi++)
#pragma unroll
                    for (int hh = 0; hh < 2; hh++) {
                        float val = v[mi][hh] ? ds[nt * 16 + mi * 8 + h * 4 + hh * 2 + j]
                                              : CUDART_INF_F;
                        m = fminf(m, val);
                    }
#pragma unroll
                for (int o = 4; o < 32; o <<= 1) m = fminf(m, __shfl_xor_sync(0xffffffffu, m, o));
                if (g == 0) {
                    int col = nt * 16 + h * 8 + q * 2 + j;
                    atomicMin(&s_min[col], __float_as_int(m));
                }
            }
    __syncthreads();
    if (tid < 32) atomicMin((int*)&out[(size_t)n * K_ + kq * 32 + tid], s_min[tid]);
}

// ---------------- launch ----------------
extern "C" void kernel_launch(void* const* d_in, const int* in_sizes, int n_in,
                              void* d_out, int out_size) {
    const float* x  = (const float*)d_in[0];   // (64, 8, 2048)
    const float* sh = (const float*)d_in[1];   // (8, 128, 64)
    float* out = (float*)d_out;                // (64, 1, 128)

    cudaFuncSetAttribute(min_dist_kernel, cudaFuncAttributeMaxDynamicSharedMemorySize, SM_TOTAL);

    prep_kernel<<<576, 512>>>(x, sh, out);
    min_dist_kernel<<<dim3(NWT, 4, N_), 128, SM_TOTAL>>>(x, out);
}